// round 15
// baseline (speedup 1.0000x reference)
#include <cuda_runtime.h>
#include <cstdint>

#define BB 4
#define NN 8192
#define FF 64
#define EE 65536
#define KK 4096
#define NW 256   // NN/32
#define KW 128   // KK/32
#define TGT (NN-KK)
#define FULLM 0xffffffffu
#define NBLK 128   // radix sort tiles per batch (512 keys each)

// ---------------- device scratch (static; no allocations) ----------------
__device__ unsigned long long g_keys[2][BB][EE];   // ping-pong
__device__ unsigned char g_ok[BB][EE];
__device__ unsigned g_sedge[BB][EE];               // packed (a | b<<13 | ok<<26), interior-first sorted
__device__ float g_vn[BB][NN];
__device__ int g_mask[BB][NN];
__device__ int g_m[BB][NN + 128];                  // +128 dummy slots for branchless greedy
__device__ int g_rank[BB][NN];
__device__ int g_gstart[BB][KK + 1];
__device__ unsigned short g_gsrc[BB][NN];
__device__ unsigned g_histM[4][BB][256 * NBLK];    // per-pass histograms, digit-major [d*NBLK+blk]
__device__ unsigned g_histS[BB][256 * NBLK];       // scanned, TRANSPOSED [blk*256+d]
__device__ unsigned g_Ab[BB][NN][NW];              // 32 MB : row-major bits of A
__device__ unsigned g_G1[BB][KK][NW];              // 16 MB : row-merged
__device__ unsigned g_G1T[BB][NN][KW];             // 16 MB : transpose of G1
__device__ unsigned g_G2[BB][KK][KW];              // 8 MB  : col-merged (transposed final)
__device__ unsigned g_M2[BB][KK][KW];              // 8 MB  : final K x K bits (row-major)

// ---------------- utils ----------------
__device__ __forceinline__ unsigned warpScanIncl(unsigned v) {
    int lane = threadIdx.x & 31;
#pragma unroll
    for (int o = 1; o < 32; o <<= 1) {
        unsigned n = __shfl_up_sync(FULLM, v, o);
        if (lane >= o) v += n;
    }
    return v;
}

__device__ __forceinline__ unsigned blockScanExcl1024(unsigned v, unsigned* s_tmp, unsigned* total) {
    int tid = threadIdx.x, lane = tid & 31, wid = tid >> 5;
    __syncthreads();
    unsigned inc = warpScanIncl(v);
    if (lane == 31) s_tmp[wid] = inc;
    __syncthreads();
    if (wid == 0) {
        unsigned w = s_tmp[lane];
        unsigned wi = warpScanIncl(w);
        s_tmp[lane] = wi - w;
        if (lane == 31) s_tmp[32] = wi;
    }
    __syncthreads();
    *total = s_tmp[32];
    return inc - v + s_tmp[wid];
}

// ---------------- 1. vertex squared norms (XLA-order) + init m + zero hists ------------
__global__ void k_vnorm(const float* __restrict__ image) {
    int idx = blockIdx.x * blockDim.x + threadIdx.x;
    if (idx >= BB * NN) return;
    unsigned* hz = &g_histM[0][0][0];
#pragma unroll
    for (int z = 0; z < 16; z++) hz[idx * 16 + z] = 0;
    const float* row = image + (size_t)idx * FF;
    float p[32];
#pragma unroll
    for (int l = 0; l < 32; l++) {
        float a = row[l], c = row[l + 32];
        p[l] = __fadd_rn(__fmul_rn(a, a), __fmul_rn(c, c));
    }
#pragma unroll
    for (int off = 16; off >= 1; off >>= 1) {
#pragma unroll
        for (int l = 0; l < 16; l++) {
            if (l < off) p[l] = __fadd_rn(p[l], p[l + off]);
        }
    }
    g_vn[0][idx] = p[0];
    g_m[idx >> 13][idx & (NN - 1)] = idx & (NN - 1);
}

// ---------------- 2. keys (boundary to tail) + fused pass-0 histogram ----------------
__global__ void k_keys(const int* __restrict__ edges, const float* __restrict__ vs) {
    int idx = blockIdx.x * blockDim.x + threadIdx.x;
    int b = idx >> 16, e = idx & (EE - 1);
    if (b >= BB) return;
    int a = edges[(size_t)b * 2 * EE + e];
    int v1 = edges[(size_t)b * 2 * EE + EE + e];
    float c = __fadd_rn(g_vn[b][a], g_vn[b][v1]);
    float ax = vs[((size_t)b * NN + a) * 2 + 0], ay = vs[((size_t)b * NN + a) * 2 + 1];
    float bx = vs[((size_t)b * NN + v1) * 2 + 0], by = vs[((size_t)b * NN + v1) * 2 + 1];
    bool bndA = (ax < 0.05f) | (ax > 0.95f) | (ay < 0.05f) | (ay > 0.95f);
    bool bndB = (bx < 0.05f) | (bx > 0.95f) | (by < 0.05f) | (by > 0.95f);
    unsigned okv = (unsigned)(!(bndA | bndB));
    g_ok[b][e] = (unsigned char)okv;
    unsigned hi = okv ? __float_as_uint(c) : 0xFFFFFFFFu;
    g_keys[0][b][e] = ((unsigned long long)hi << 32) | (unsigned)e;
    atomicAdd(&g_histM[0][b][(hi & 255u) * NBLK + (e >> 9)], 1u);
}

// ---------------- 3a. scan pass-p histogram; write TRANSPOSED for coalesced scat -------
__global__ void __launch_bounds__(1024) k_scan(int p) {
    __shared__ unsigned s_tmp[33];
    int b = blockIdx.x, t = threadIdx.x;
    const unsigned* H = g_histM[p][b];
    unsigned v[32]; unsigned sum = 0;
    int base = t * 32;
#pragma unroll
    for (int i = 0; i < 32; i++) { v[i] = H[base + i]; sum += v[i]; }
    unsigned tot;
    unsigned ex = blockScanExcl1024(sum, s_tmp, &tot);
    unsigned run = ex;
#pragma unroll
    for (int i = 0; i < 32; i++) {
        int h = base + i;
        g_histS[b][(h & (NBLK - 1)) * 256 + (h >> 7)] = run;
        run += v[i];
    }
}

// ---------------- 3b. stable scatter, dual-element single prefix round ------------------
__global__ void __launch_bounds__(256) k_scat(int p, const int* __restrict__ edges, int last) {
    __shared__ unsigned s_wcnt0[8 * 256];
    __shared__ unsigned s_wcnt1[8 * 256];
    __shared__ unsigned s_pre0[8 * 256];
    __shared__ unsigned s_pre1[8 * 256];
    __shared__ unsigned s_base[256];
    int b = blockIdx.y, blk = blockIdx.x, t = threadIdx.x, lane = t & 31, w = t >> 5;
    const unsigned long long* src = g_keys[p & 1][b];
    unsigned long long* dst = g_keys[(p + 1) & 1][b];
    int sh = 32 + 8 * p;
#pragma unroll
    for (int k = lane; k < 256; k += 32) { s_wcnt0[w * 256 + k] = 0; s_wcnt1[w * 256 + k] = 0; }
    s_base[t] = g_histS[b][blk * 256 + t];
    unsigned long long k0 = src[blk * 512 + t], k1 = src[blk * 512 + 256 + t];
    unsigned d0 = (unsigned)(k0 >> sh) & 255u;
    unsigned d1 = (unsigned)(k1 >> sh) & 255u;
    unsigned m0 = __match_any_sync(FULLM, d0);
    unsigned m1 = __match_any_sync(FULLM, d1);
    unsigned below = (1u << lane) - 1u;
    unsigned rw0 = __popc(m0 & below);
    unsigned rw1 = __popc(m1 & below);
    if (rw0 == 0) s_wcnt0[w * 256 + d0] = __popc(m0);
    if (rw1 == 0) s_wcnt1[w * 256 + d1] = __popc(m1);
    __syncthreads();
    unsigned run = s_base[t];
#pragma unroll
    for (int w2 = 0; w2 < 8; w2++) { s_pre0[w2 * 256 + t] = run; run += s_wcnt0[w2 * 256 + t]; }
#pragma unroll
    for (int w2 = 0; w2 < 8; w2++) { s_pre1[w2 * 256 + t] = run; run += s_wcnt1[w2 * 256 + t]; }
    __syncthreads();
    unsigned pos0 = s_pre0[w * 256 + d0] + rw0;
    unsigned pos1 = s_pre1[w * 256 + d1] + rw1;
    if (!last) {
        dst[pos0] = k0;
        dst[pos1] = k1;
        unsigned e0 = (unsigned)(k0 >> (sh + 8)) & 255u;
        unsigned e1 = (unsigned)(k1 >> (sh + 8)) & 255u;
        atomicAdd(&g_histM[p + 1][b][e0 * NBLK + (pos0 >> 9)], 1u);
        atomicAdd(&g_histM[p + 1][b][e1 * NBLK + (pos1 >> 9)], 1u);
    } else {
        unsigned eid0 = (unsigned)(k0 & 0xffffffffu);
        unsigned eid1 = (unsigned)(k1 & 0xffffffffu);
        unsigned a0 = (unsigned)edges[(size_t)b * 2 * EE + eid0];
        unsigned v0 = (unsigned)edges[(size_t)b * 2 * EE + EE + eid0];
        unsigned a1 = (unsigned)edges[(size_t)b * 2 * EE + eid1];
        unsigned v1 = (unsigned)edges[(size_t)b * 2 * EE + EE + eid1];
        g_sedge[b][pos0] = a0 | (v0 << 13) | ((unsigned)g_ok[b][eid0] << 26);
        g_sedge[b][pos1] = a1 | (v1 << 13) | ((unsigned)g_ok[b][eid1] << 26);
    }
}

// ---------------- 4. greedy collapse: 128-edge BRANCHLESS windows ----------------------
// slot s (0..3), lane l -> edge index w*128 + s*32 + l. Non-tentative slots publish to
// private dummy slots NN+sid. 8-bit epoch tags: aliasing (w>=256) only adds conservative
// false conflicts -> serial fallback -> still exact.
__global__ void k_greedy() {
    __shared__ unsigned char s_mask[NN + 128];
    __shared__ unsigned char s_tagA[NN + 128];
    __shared__ unsigned char s_tagB[NN + 128];
    __shared__ unsigned char s_own[NN + 128];
    int bb = blockIdx.x, lane = threadIdx.x;
    for (int i = lane; i < NN + 128; i += 32) { s_mask[i] = 1; s_tagA[i] = 0xFF; s_tagB[i] = 0xFF; }
    __syncwarp();
    int nk = 0;
    const int W = EE / 128;   // 512 windows
    int sid[4], dmy[4];
    unsigned cur[4], nxt[4];
#pragma unroll
    for (int s = 0; s < 4; s++) {
        sid[s] = s * 32 + lane; dmy[s] = NN + sid[s];
        cur[s] = g_sedge[bb][s * 32 + lane];
        nxt[s] = g_sedge[bb][128 + s * 32 + lane];
    }
    for (int w = 0; w < W; w++) {
        unsigned pf[4] = {0, 0, 0, 0};
        if (w + 2 < W) {
#pragma unroll
            for (int s = 0; s < 4; s++) pf[s] = g_sedge[bb][(w + 2) * 128 + s * 32 + lane];
        }
        int a[4], b[4], t[4], ma[4], mb[4];
#pragma unroll
        for (int s = 0; s < 4; s++) { a[s] = cur[s] & 8191; b[s] = (cur[s] >> 13) & 8191; }
#pragma unroll
        for (int s = 0; s < 4; s++) { ma[s] = s_mask[a[s]]; mb[s] = s_mask[b[s]]; }
#pragma unroll
        for (int s = 0; s < 4; s++) t[s] = ((cur[s] >> 26) & 1) & ma[s] & mb[s];
        unsigned T[4];
#pragma unroll
        for (int s = 0; s < 4; s++) T[s] = __ballot_sync(FULLM, t[s]);
        if (T[0] | T[1] | T[2] | T[3]) {
            unsigned char w8 = (unsigned char)w;
            int ia[4], ib[4];
#pragma unroll
            for (int s = 0; s < 4; s++) { ia[s] = t[s] ? a[s] : dmy[s]; ib[s] = t[s] ? b[s] : dmy[s]; }
#pragma unroll
            for (int s = 0; s < 4; s++) {
                s_tagA[ia[s]] = w8; s_tagB[ib[s]] = w8; s_own[ib[s]] = (unsigned char)sid[s];
            }
            __syncwarp();
            int l[4];
#pragma unroll
            for (int s = 0; s < 4; s++) l[s] = s_own[ib[s]] != (unsigned char)sid[s];
#pragma unroll
            for (int s = 0; s < 4; s++) s_tagA[l[s] ? b[s] : dmy[s]] = w8;
            __syncwarp();
            int f[4];
#pragma unroll
            for (int s = 0; s < 4; s++)
                f[s] = t[s] & (l[s] | (s_tagA[b[s]] == w8) | (s_tagB[a[s]] == w8));
            unsigned I[4];
#pragma unroll
            for (int s = 0; s < 4; s++) I[s] = __ballot_sync(FULLM, f[s]);
            int cnt = __popc(T[0]) + __popc(T[1]) + __popc(T[2]) + __popc(T[3]);
            unsigned acc[4] = {0, 0, 0, 0};
            if (nk + cnt <= TGT) {
                if (!(I[0] | I[1] | I[2] | I[3])) {
#pragma unroll
                    for (int s = 0; s < 4; s++) acc[s] = T[s];
                    nk += cnt;
                } else {
#pragma unroll
                    for (int s = 0; s < 4; s++) { acc[s] = T[s] & ~I[s]; nk += __popc(acc[s]); }
#pragma unroll
                    for (int s = 0; s < 4; s++) {
                        unsigned TT = I[s];
                        while (TT) {
                            int t2 = __ffs(TT) - 1; TT &= TT - 1;
                            int at = __shfl_sync(FULLM, a[s], t2);
                            int bt = __shfl_sync(FULLM, b[s], t2);
                            int hit = 0;
#pragma unroll
                            for (int s2 = 0; s2 < 4; s2++)
                                hit |= ((acc[s2] >> lane) & 1) && (b[s2] == at || b[s2] == bt);
                            unsigned conf = __ballot_sync(FULLM, hit);
                            if (!conf) { acc[s] |= 1u << t2; nk++; }
                        }
                    }
                }
            } else {
#pragma unroll
                for (int s = 0; s < 4; s++) {
                    unsigned TT = T[s];
                    while (TT) {
                        int t2 = __ffs(TT) - 1; TT &= TT - 1;
                        int at = __shfl_sync(FULLM, a[s], t2);
                        int bt = __shfl_sync(FULLM, b[s], t2);
                        int hit = 0;
#pragma unroll
                        for (int s2 = 0; s2 < 4; s2++)
                            hit |= ((acc[s2] >> lane) & 1) && (b[s2] == at || b[s2] == bt);
                        unsigned conf = __ballot_sync(FULLM, hit);
                        if (!conf && nk < TGT) { acc[s] |= 1u << t2; nk++; }
                    }
                }
            }
#pragma unroll
            for (int s = 0; s < 4; s++) {
                int A = (acc[s] >> lane) & 1;
                s_mask[A ? b[s] : dmy[s]] = 0;
                g_m[bb][A ? b[s] : dmy[s]] = a[s];
            }
            __syncwarp();
            if (nk >= TGT) break;
        }
#pragma unroll
        for (int s = 0; s < 4; s++) { cur[s] = nxt[s]; nxt[s] = pf[s]; }
    }
    for (int i = lane; i < NN; i += 32) g_mask[bb][i] = s_mask[i];
}

// ---------------- 5. alive ranks + group CSR ----------------
__global__ void __launch_bounds__(1024) k_compact() {
    __shared__ unsigned s_tmp[33];
    __shared__ int s_cnt[KK];
    __shared__ int s_cur[KK];
    int b = blockIdx.x, tid = threadIdx.x;
    int base = tid * 8;
    unsigned mk[8]; unsigned c = 0;
#pragma unroll
    for (int i = 0; i < 8; i++) { mk[i] = (unsigned)g_mask[b][base + i]; c += mk[i]; }
    unsigned tot;
    unsigned ex = blockScanExcl1024(c, s_tmp, &tot);
    int run = (int)ex;
#pragma unroll
    for (int i = 0; i < 8; i++) { g_rank[b][base + i] = run; run += (int)mk[i]; }
    __syncthreads();
    for (int r = tid; r < KK; r += 1024) s_cnt[r] = 0;
    __syncthreads();
    for (int j = tid; j < NN; j += 1024) {
        int t = g_m[b][j];
        if (g_mask[b][t]) { int r = g_rank[b][t]; if (r < KK) atomicAdd(&s_cnt[r], 1); }
    }
    __syncthreads();
    int i4 = tid * 4; unsigned cv[4]; unsigned sum = 0;
#pragma unroll
    for (int i = 0; i < 4; i++) { cv[i] = (unsigned)s_cnt[i4 + i]; sum += cv[i]; }
    unsigned tot2;
    unsigned ex2 = blockScanExcl1024(sum, s_tmp, &tot2);
    int run2 = (int)ex2;
#pragma unroll
    for (int i = 0; i < 4; i++) { g_gstart[b][i4 + i] = run2; s_cur[i4 + i] = run2; run2 += (int)cv[i]; }
    if (tid == 1023) g_gstart[b][KK] = run2;
    __syncthreads();
    for (int j = tid; j < NN; j += 1024) {
        int t = g_m[b][j];
        if (g_mask[b][t]) {
            int r = g_rank[b][t];
            if (r < KK) { int pos = atomicAdd(&s_cur[r], 1); g_gsrc[b][pos] = (unsigned short)j; }
        }
    }
}

// ---------------- 6. pack A (f32 0/1) -> row-major bits via warp ballot ----------------
__global__ void __launch_bounds__(256) k_pack(const float* __restrict__ A) {
    int gw = (blockIdx.x * 256 + threadIdx.x) >> 5;
    int lane = threadIdx.x & 31;
    const float* base = A + (size_t)gw * 1024;
    unsigned myw = 0;
#pragma unroll
    for (int t = 0; t < 32; t++) {
        float v = base[t * 32 + lane];
        unsigned bal = __ballot_sync(FULLM, v != 0.0f);
        if (lane == t) myw = bal;
    }
    ((unsigned*)g_Ab)[(size_t)gw * 32 + lane] = myw;
}

// ---------------- 7. G1[r] = OR of A-bit rows in group(r)  (row merge) ----------------
__global__ void __launch_bounds__(1024) k_G1() {
    int b = blockIdx.y;
    int c = blockIdx.x * 4 + (threadIdx.x >> 8);
    int w = threadIdx.x & 255;
    int s = g_gstart[b][c], e = g_gstart[b][c + 1];
    unsigned v = 0;
    for (int i = s; i < e; i++) v |= g_Ab[b][g_gsrc[b][i]][w];
    g_G1[b][c][w] = v;
}

// ---------------- 8. bit transpose G1 (K x N) -> G1T (N x K) ----------------
__global__ void __launch_bounds__(1024) k_transT() {
    __shared__ __align__(16) unsigned wt[256 * 5];
    __shared__ __align__(16) unsigned outS[1024];
    int b = blockIdx.z, ct = blockIdx.y, jt = blockIdx.x;
    int tid = threadIdx.x;
    {
        int r = tid >> 2, w4 = tid & 3;
        wt[r * 5 + w4] = g_G1[b][ct * 256 + r][jt * 4 + w4];
    }
    __syncthreads();
    int w = tid >> 5, lane = tid & 31;
    int jw = w >> 3, iw = w & 7;
    unsigned s = wt[(iw * 32 + lane) * 5 + jw];
    unsigned myword = 0;
#pragma unroll 1
    for (int k = 0; k < 32; k++) {
        unsigned bt = __ballot_sync(FULLM, (s >> k) & 1);
        if (lane == k) myword = bt;
    }
    outS[(jw * 32 + lane) * 8 + iw] = myword;
    __syncthreads();
    int j = tid >> 3, ww = tid & 7;
    g_G1T[b][jt * 128 + j][ct * 8 + ww] = outS[tid];
}

// ---------------- 9. G2[c] = OR of G1T rows in group(c)  (col merge) ----------------
__global__ void __launch_bounds__(1024) k_G2() {
    int b = blockIdx.y;
    int r = blockIdx.x * 8 + (threadIdx.x >> 7);
    int w = threadIdx.x & 127;
    int s = g_gstart[b][r], e = g_gstart[b][r + 1];
    unsigned v = 0;
    for (int i = s; i < e; i++) v |= g_G1T[b][g_gsrc[b][i]][w];
    g_G2[b][r][w] = v;
}

// ---------------- 10. final K x K bit transpose: G2 -> M2 ----------------
__global__ void __launch_bounds__(1024) k_transKK() {
    __shared__ __align__(16) unsigned wt[256 * 5];
    __shared__ __align__(16) unsigned outS[1024];
    int b = blockIdx.z, ct = blockIdx.y, jt = blockIdx.x;
    int tid = threadIdx.x;
    {
        int r = tid >> 2, w4 = tid & 3;
        wt[r * 5 + w4] = g_G2[b][ct * 256 + r][jt * 4 + w4];
    }
    __syncthreads();
    int w = tid >> 5, lane = tid & 31;
    int jw = w >> 3, iw = w & 7;
    unsigned s = wt[(iw * 32 + lane) * 5 + jw];
    unsigned myword = 0;
#pragma unroll 1
    for (int k = 0; k < 32; k++) {
        unsigned bt = __ballot_sync(FULLM, (s >> k) & 1);
        if (lane == k) myword = bt;
    }
    outS[(jw * 32 + lane) * 8 + iw] = myword;
    __syncthreads();
    int j = tid >> 3, ww = tid & 7;
    g_M2[b][jt * 128 + j][ct * 8 + ww] = outS[tid];
}

// ---------------- 11a. pooled features (pack-independent; before join) ----------------
__global__ void k_feat(const float* __restrict__ image, float* __restrict__ out) {
    int b = blockIdx.y;
    int idx = blockIdx.x * 256 + threadIdx.x;
    int f = idx & (FF - 1);
    int r = idx >> 6;
    int s = g_gstart[b][r], e = g_gstart[b][r + 1];
    float acc = 0.f;
    for (int i = s; i < e; i++) {
        int j = g_gsrc[b][i];
        acc += image[((size_t)b * NN + j) * FF + f];
    }
    out[(size_t)BB * KK * KK + ((size_t)b * KK + r) * FF + f] = acc;
}

// ---------------- 11b. expand bits -> float (diag cleared) ----------------
__global__ void k_expand(float* __restrict__ out) {
    int b = blockIdx.y;
    int idx = blockIdx.x * 256 + threadIdx.x;
    int r = idx >> 10;
    int c4 = (idx & 1023) << 2;
    unsigned wv = g_M2[b][r][c4 >> 5];
    int sh = c4 & 31;
    float4 o;
    o.x = (((wv >> (sh + 0)) & 1) && (r != c4 + 0)) ? 1.f : 0.f;
    o.y = (((wv >> (sh + 1)) & 1) && (r != c4 + 1)) ? 1.f : 0.f;
    o.z = (((wv >> (sh + 2)) & 1) && (r != c4 + 2)) ? 1.f : 0.f;
    o.w = (((wv >> (sh + 3)) & 1) && (r != c4 + 3)) ? 1.f : 0.f;
    ((float4*)out)[((size_t)b * KK + r) * (KK / 4) + (idx & 1023)] = o;
}

// ---------------- launch ----------------
extern "C" void kernel_launch(void* const* d_in, const int* in_sizes, int n_in,
                              void* d_out, int out_size) {
    const float* adj = (const float*)d_in[0];
    const float* image = (const float*)d_in[1];
    const float* vs = (const float*)d_in[2];
    const int* edges = (const int*)d_in[3];
    float* out = (float*)d_out;

    static cudaStream_t s1 = nullptr;
    static cudaEvent_t evF = nullptr, evJ = nullptr;
    if (!s1) {
        cudaStreamCreateWithFlags(&s1, cudaStreamNonBlocking);
        cudaEventCreateWithFlags(&evF, cudaEventDisableTiming);
        cudaEventCreateWithFlags(&evJ, cudaEventDisableTiming);
    }

    cudaEventRecord(evF, 0);

    k_vnorm<<<(BB * NN) / 256, 256>>>(image);                 // #1 (also zeros hists)
    k_keys<<<(BB * EE) / 256, 256>>>(edges, vs);              // #2 (fused pass-0 count)
    k_scan<<<BB, 1024>>>(0);                                  // #3
    k_scat<<<dim3(NBLK, BB), 256>>>(0, edges, 0);             // #4  <- ncu sample target
    for (int p = 1; p < 4; p++) {
        k_scan<<<BB, 1024>>>(p);
        k_scat<<<dim3(NBLK, BB), 256>>>(p, edges, p == 3);
    }
    k_greedy<<<BB, 32>>>();

    cudaStreamWaitEvent(s1, evF, 0);
    k_pack<<<32768, 256, 0, s1>>>(adj);                       // overlaps from capture start

    k_compact<<<BB, 1024>>>();
    k_feat<<<dim3((KK * FF) / 256, BB), 256>>>(image, out);   // pack-independent

    cudaEventRecord(evJ, s1);
    cudaStreamWaitEvent(0, evJ, 0);

    k_G1<<<dim3(KK / 4, BB), 1024>>>();
    k_transT<<<dim3(NN / 128, KK / 256, BB), 1024>>>();
    k_G2<<<dim3(KK / 8, BB), 1024>>>();
    k_transKK<<<dim3(KK / 128, KK / 256, BB), 1024>>>();
    k_expand<<<dim3((KK * KK / 4) / 256, BB), 256>>>(out);
}